// round 16
// baseline (speedup 1.0000x reference)
#include <cuda_runtime.h>
#include <cstdint>

typedef unsigned long long ull;

// ---- packed f32x2 helpers (sm_103a) ----
__device__ __forceinline__ ull ffma2(ull a, ull b, ull c) {
    ull d;
    asm("fma.rn.f32x2 %0, %1, %2, %3;" : "=l"(d) : "l"(a), "l"(b), "l"(c));
    return d;
}
__device__ __forceinline__ ull fmul2(ull a, ull b) {
    ull d;
    asm("mul.rn.f32x2 %0, %1, %2;" : "=l"(d) : "l"(a), "l"(b));
    return d;
}
__device__ __forceinline__ ull fadd2(ull a, ull b) {
    ull d;
    asm("add.rn.f32x2 %0, %1, %2;" : "=l"(d) : "l"(a), "l"(b));
    return d;
}
__device__ __forceinline__ ull pack2(float lo, float hi) {
    ull d;
    asm("mov.b64 %0, {%1, %2};" : "=l"(d) : "f"(lo), "f"(hi));
    return d;
}
__device__ __forceinline__ ull dup2(float v) { return pack2(v, v); }
__device__ __forceinline__ float2 unpack2(ull v) {
    float lo, hi;
    asm("mov.b64 {%0, %1}, %2;" : "=f"(lo), "=f"(hi) : "l"(v));
    return make_float2(lo, hi);
}
__device__ __forceinline__ ull shflx(ull v, int m) {
    return __shfl_xor_sync(0xffffffffu, v, m);
}

constexpr int D_DIM        = 1024;
constexpr int THREADS      = 256;
constexpr int ROWS_PER_BLK = 64;
constexpr int BATCH        = 32;              // 32-row batches -> 4 barriers/CTA (was 8)
constexpr int NGRP         = 32;              // 8-lane groups over 256 threads
constexpr int SLOTS        = BATCH * 3;       // 96 (row, f32x2-pair)
constexpr int PSTRIDE      = SLOTS + 1;       // 97, odd stride -> conflict-free columns

__global__ void __launch_bounds__(THREADS, 4)
q6_kernel(const float* __restrict__ x,
          const float* __restrict__ W,
          const float* __restrict__ proto,
          const float* __restrict__ hs,
          float* __restrict__ out)
{
    // partials: [g=0..31][row*3+pair]
    __shared__ ull   part[NGRP * PSTRIDE];    // 24.8 KB
    __shared__ ull   zz[SLOTS];
    __shared__ float pn[8][6];
    __shared__ float s3_sh;

    const int tid  = threadIdx.x;
    const int lane = tid & 31;
    const int warp = tid >> 5;
    const int col  = tid * 4;        // this thread owns columns [col, col+4)

    // ---- one-time block init: normalized prototypes + fused scale ----
    if (tid < 8) {
        float v[6]; float ss = 0.f;
        #pragma unroll
        for (int k = 0; k < 6; ++k) { v[k] = proto[tid * 6 + k]; ss += v[k] * v[k]; }
        float n = fmaxf(sqrtf(ss), 1e-12f);
        #pragma unroll
        for (int k = 0; k < 6; ++k) pn[tid][k] = v[k] / n;
    }
    if (tid == 8) s3_sh = 3.0f * hs[0];   // softmax(-hs*(6-6d)/2) == softmax(3*hs*d)

    // ---- W slice for this thread's 4 columns, packed (k0,k1),(k2,k3),(k4,k5) ----
    ull wp[4][3];
    {
        float4 w4[6];
        #pragma unroll
        for (int k = 0; k < 6; ++k)
            w4[k] = *reinterpret_cast<const float4*>(W + k * D_DIM + col);
        #pragma unroll
        for (int p = 0; p < 3; ++p) {
            wp[0][p] = pack2(w4[2*p].x, w4[2*p+1].x);
            wp[1][p] = pack2(w4[2*p].y, w4[2*p+1].y);
            wp[2][p] = pack2(w4[2*p].z, w4[2*p+1].z);
            wp[3][p] = pack2(w4[2*p].w, w4[2*p+1].w);
        }
    }

    const int rowbase = blockIdx.x * ROWS_PER_BLK;

    for (int b = 0; b < ROWS_PER_BLK / BATCH; ++b) {
        const int    r0 = rowbase + b * BATCH;
        const float* xp = x + (size_t)r0 * D_DIM + col;

        // ---------------- phase 1: partial dots + 3-round butterfly ----------------
        #pragma unroll
        for (int r = 0; r < BATCH; r += 4) {
            float4 xv[4];
            #pragma unroll
            for (int u = 0; u < 4; ++u)   // batch 4 streaming loads -> MLP=4
                xv[u] = __ldcs(reinterpret_cast<const float4*>(xp + (size_t)(r + u) * D_DIM));
            #pragma unroll
            for (int u = 0; u < 4; ++u) {
                ull xx = dup2(xv[u].x);
                ull a0 = fmul2(xx, wp[0][0]);
                ull a1 = fmul2(xx, wp[0][1]);
                ull a2 = fmul2(xx, wp[0][2]);
                xx = dup2(xv[u].y);
                a0 = ffma2(xx, wp[1][0], a0);
                a1 = ffma2(xx, wp[1][1], a1);
                a2 = ffma2(xx, wp[1][2], a2);
                xx = dup2(xv[u].z);
                a0 = ffma2(xx, wp[2][0], a0);
                a1 = ffma2(xx, wp[2][1], a1);
                a2 = ffma2(xx, wp[2][2], a2);
                xx = dup2(xv[u].w);
                a0 = ffma2(xx, wp[3][0], a0);
                a1 = ffma2(xx, wp[3][1], a1);
                a2 = ffma2(xx, wp[3][2], a2);

                // 3-round butterfly: lane%8==0 holds 8-lane (32-column) group sum
                a0 = fadd2(a0, shflx(a0, 1));
                a1 = fadd2(a1, shflx(a1, 1));
                a2 = fadd2(a2, shflx(a2, 1));
                a0 = fadd2(a0, shflx(a0, 2));
                a1 = fadd2(a1, shflx(a1, 2));
                a2 = fadd2(a2, shflx(a2, 2));
                a0 = fadd2(a0, shflx(a0, 4));
                a1 = fadd2(a1, shflx(a1, 4));
                a2 = fadd2(a2, shflx(a2, 4));

                if ((lane & 7) == 0) {
                    const int g = warp * 4 + (lane >> 3);   // 0..31
                    ull* dst = part + g * PSTRIDE + (r + u) * 3;
                    dst[0] = a0; dst[1] = a1; dst[2] = a2;
                }
            }
        }
        __syncthreads();

        // ------- phase 2: 96 threads sum 32 group partials per (row, pair), MLP=8 -----
        if (tid < SLOTS) {
            ull s[8];
            #pragma unroll
            for (int j = 0; j < 8; ++j)               // 8 independent loads in flight
                s[j] = part[j * PSTRIDE + tid];
            #pragma unroll
            for (int g = 8; g < NGRP; g += 8) {
                #pragma unroll
                for (int j = 0; j < 8; ++j)
                    s[j] = fadd2(s[j], part[(g + j) * PSTRIDE + tid]);
            }
            ull t0 = fadd2(fadd2(s[0], s[1]), fadd2(s[2], s[3]));
            ull t1 = fadd2(fadd2(s[4], s[5]), fadd2(s[6], s[7]));
            zz[tid] = fadd2(t0, t1);
        }
        __syncthreads();

        // ---------------- phase 3: epilogue, one thread per row --------------------
        // (overlaps other warps' next-batch streaming; MUFU-based fast math)
        if (tid < BATCH) {
            float z[6];
            #pragma unroll
            for (int p = 0; p < 3; ++p) {
                float2 v = unpack2(zz[tid * 3 + p]);
                z[2*p] = v.x; z[2*p + 1] = v.y;
            }
            float ss = 0.f;
            #pragma unroll
            for (int k = 0; k < 6; ++k) {
                float e2 = __expf(2.0f * z[k]);            // tanh = 1 - 2/(e^2x+1)
                z[k] = 1.0f - __fdividef(2.0f, e2 + 1.0f);
                ss += z[k] * z[k];
            }
            const float sc = __fdividef(s3_sh, fmaxf(sqrtf(ss), 1e-6f));

            float e[8]; float sum = 0.f;
            #pragma unroll
            for (int p = 0; p < 8; ++p) {
                float d = 0.f;
                #pragma unroll
                for (int k = 0; k < 6; ++k) d += z[k] * pn[p][k];
                e[p] = __expf(sc * d);
                sum += e[p];
            }
            const float rs  = __fdividef(1.0f, sum);
            const int   row = r0 + tid;
            float4* op = reinterpret_cast<float4*>(out + (size_t)row * 8);
            op[0] = make_float4(e[0]*rs, e[1]*rs, e[2]*rs, e[3]*rs);
            op[1] = make_float4(e[4]*rs, e[5]*rs, e[6]*rs, e[7]*rs);
        }
    }
}

extern "C" void kernel_launch(void* const* d_in, const int* in_sizes, int n_in,
                              void* d_out, int out_size) {
    const float* x     = (const float*)d_in[0];
    const float* W     = (const float*)d_in[1];
    const float* proto = (const float*)d_in[2];
    const float* hs    = (const float*)d_in[3];
    float* out = (float*)d_out;

    const int n_rows = in_sizes[0] / D_DIM;          // 32768
    const int grid   = n_rows / ROWS_PER_BLK;        // 512
    q6_kernel<<<grid, THREADS>>>(x, W, proto, hs, out);
}